// round 9
// baseline (speedup 1.0000x reference)
#include <cuda_runtime.h>
#include <math.h>
#include <stdint.h>

#define B_   8
#define N_   2048
#define M_   512
#define C_   256
#define NR_  4
#define CNT_ (B_*NR_*N_)

// ---------------- scratch ----------------
__device__ float g_G [B_*NR_*M_*C_];   // [z][m][o] o-contiguous
__device__ float g_y1[B_*NR_*C_*N_];   // [z][c][n] n-contiguous
__device__ int   g_idx[B_*N_*3];
__device__ float g_w  [B_*N_*3];
__device__ float g_s1[C_], g_q1[C_], g_s2[C_], g_q2[C_];
__device__ float g_scale1[C_], g_bias1[C_], g_scale2[C_], g_bias2[C_];

// ---------------- helpers ----------------
__device__ __forceinline__ unsigned f2tf(float f) {
    unsigned u; asm("cvt.rna.tf32.f32 %0, %1;" : "=r"(u) : "f"(f)); return u;
}
__device__ __forceinline__ void mma8(float* c, const unsigned* a, const unsigned* b) {
    asm volatile("mma.sync.aligned.m16n8k8.row.col.f32.tf32.tf32.f32 "
        "{%0,%1,%2,%3}, {%4,%5,%6,%7}, {%8,%9}, {%0,%1,%2,%3};"
        : "+f"(c[0]), "+f"(c[1]), "+f"(c[2]), "+f"(c[3])
        : "r"(a[0]), "r"(a[1]), "r"(a[2]), "r"(a[3]), "r"(b[0]), "r"(b[1]));
}
__device__ __forceinline__ void cp16(float* dst, const float* src) {
    uint32_t d;
    asm("{ .reg .u64 t; cvta.to.shared.u64 t, %1; cvt.u32.u64 %0, t; }" : "=r"(d) : "l"(dst));
    asm volatile("cp.async.ca.shared.global [%0], [%1], 16;" :: "r"(d), "l"(src) : "memory");
}
#define CP_COMMIT() asm volatile("cp.async.commit_group;" ::: "memory")
#define CP_WAIT(n)  asm volatile("cp.async.wait_group %0;" :: "n"(n) : "memory")

// ---------------- smem layout (floats) ----------------
#define AP 20                  // A stage pitch: 16 k + 4 pad  (banks 20g+t all distinct)
#define BP 136                 // B stage pitch: 128 n + 8 pad (banks 8t+g all distinct)
#define YP 257                 // Ys pitch (odd -> scalar passes conflict-free)
#define STGF 7296              // stage stride: A 256*20=5120 + B 16*136=2176
#define OFF_B 5120
#define OFF_S (128*257)        // 32896 : stats sum (256)
#define OFF_Q (OFF_S + 256)
#define OFF_W (OFF_Q + 256)    // interp weights (384)
#define OFF_I (OFF_W + 384)    // interp indices (384, int view)
#define SMEMF (OFF_I + 384)    // 34176 floats = 136704 bytes
#define SMEM_BYTES (SMEMF * 4)

// ---------------- small kernels ----------------
__global__ void zero_stats_kernel() {
    int t = threadIdx.x;
    g_s1[t] = 0.f; g_q1[t] = 0.f; g_s2[t] = 0.f; g_q2[t] = 0.f;
}

__global__ void knn_kernel(const float* __restrict__ unknown,
                           const float* __restrict__ known) {
    __shared__ float ks[M_*3];
    int b = blockIdx.y;
    const float* kb = known + (size_t)b * M_ * 3;
    for (int i = threadIdx.x; i < M_*3; i += blockDim.x) ks[i] = kb[i];
    __syncthreads();
    int n = blockIdx.x * blockDim.x + threadIdx.x;
    const float* u = unknown + ((size_t)b * N_ + n) * 3;
    float ux = u[0], uy = u[1], uz = u[2];
    float d0 = 3.4e38f, d1 = 3.4e38f, d2 = 3.4e38f;
    int   i0 = 0, i1 = 0, i2 = 0;
    for (int m = 0; m < M_; m++) {
        float dx = ux - ks[m*3], dy = uy - ks[m*3+1], dz = uz - ks[m*3+2];
        float d  = dx*dx + dy*dy + dz*dz;
        if (d < d2) {
            if (d < d0)      { d2=d1; i2=i1; d1=d0; i1=i0; d0=d; i0=m; }
            else if (d < d1) { d2=d1; i2=i1; d1=d;  i1=m; }
            else             { d2=d;  i2=m; }
        }
    }
    float r0 = 1.f / (sqrtf(fmaxf(d0, 0.f)) + 1e-8f);
    float r1 = 1.f / (sqrtf(fmaxf(d1, 0.f)) + 1e-8f);
    float r2 = 1.f / (sqrtf(fmaxf(d2, 0.f)) + 1e-8f);
    float inv = 1.f / (r0 + r1 + r2);
    int base = (b * N_ + n) * 3;
    g_idx[base] = i0; g_idx[base+1] = i1; g_idx[base+2] = i2;
    g_w[base] = r0*inv; g_w[base+1] = r1*inv; g_w[base+2] = r2*inv;
}

__global__ void bnfin_kernel(const float* __restrict__ gamma,
                             const float* __restrict__ beta, int which) {
    int t = threadIdx.x;
    float s = which ? g_s2[t] : g_s1[t];
    float q = which ? g_q2[t] : g_q1[t];
    float mean = s * (1.f / CNT_);
    float var  = q * (1.f / CNT_) - mean * mean;
    float sc = gamma[t] * rsqrtf(var + 1e-5f);
    float bi = beta[t] - mean * sc;
    if (which) { g_scale2[t] = sc; g_bias2[t] = bi; }
    else       { g_scale1[t] = sc; g_bias1[t] = bi; }
}

__global__ void out_kernel(float* __restrict__ out) {
    int i = blockIdx.x * blockDim.x + threadIdx.x;
    int o = (i >> 11) & 255;
    float sc = g_scale2[o], bi = g_bias2[o];
    float4 v = ((float4*)out)[i];
    v.x = fmaxf(fmaf(v.x, sc, bi), 0.f);
    v.y = fmaxf(fmaf(v.y, sc, bi), 0.f);
    v.z = fmaxf(fmaf(v.z, sc, bi), 0.f);
    v.w = fmaxf(fmaf(v.w, sc, bi), 0.f);
    ((float4*)out)[i] = v;
}

// ---------------- GEMM core pieces ----------------
// Block tile 256(o) x 128(n), K chunk 16. 8 warps as (wo 0..3) x (wn 0..1),
// warp tile 64o x 64n = 4 mtiles x 8 ntiles of m16n8k8 tf32 mma.
// A staged [o][AP] (raw fp32, direct cp.async from K-major weights).
// B staged [k][BP] (raw fp32, direct cp.async from n-contiguous activations).
// cvt.rna to tf32 happens on the fragment registers.

__device__ __forceinline__ void stageA(float* sm, int p, const float* Wsrc,
                                       int wstride, int c, int tid) {
    float* Ad = sm + p*STGF + tid*AP;
    const float* src = Wsrc + (size_t)tid * wstride + c*16;
    cp16(Ad, src); cp16(Ad+4, src+4); cp16(Ad+8, src+8); cp16(Ad+12, src+12);
}
__device__ __forceinline__ void stageB(float* sm, int p, const float* Xsrc,
                                       int cs, int c, int tid) {
    int k = tid >> 4, ng = (tid & 15) * 8;
    float* Bd = sm + p*STGF + OFF_B + k*BP + ng;
    const float* src = Xsrc + (size_t)(c*16 + k) * cs + ng;
    cp16(Bd, src); cp16(Bd+4, src+4);
}

__device__ __forceinline__ void frag_mma(const float* A, const float* Bs,
                                         int wo, int wn, int g, int t,
                                         float acc[4][8][4]) {
    #pragma unroll
    for (int ks = 0; ks < 16; ks += 8) {
        unsigned af[4][4], bf[8][2];
        #pragma unroll
        for (int mi = 0; mi < 4; mi++) {
            int orow = wo*64 + mi*16 + g;
            af[mi][0] = f2tf(A[orow*AP + ks + t]);
            af[mi][1] = f2tf(A[(orow+8)*AP + ks + t]);
            af[mi][2] = f2tf(A[orow*AP + ks + t + 4]);
            af[mi][3] = f2tf(A[(orow+8)*AP + ks + t + 4]);
        }
        #pragma unroll
        for (int ni = 0; ni < 8; ni++) {
            int nb = wn*64 + ni*8 + g;
            bf[ni][0] = f2tf(Bs[(ks+t)*BP + nb]);
            bf[ni][1] = f2tf(Bs[(ks+t+4)*BP + nb]);
        }
        #pragma unroll
        for (int mi = 0; mi < 4; mi++)
            #pragma unroll
            for (int ni = 0; ni < 8; ni++)
                mma8(acc[mi][ni], af[mi], bf[ni]);
    }
}

__device__ __forceinline__ void mainloop_cp(float* sm, const float* Wsrc, int wstride,
                                            const float* Xsrc, int cs,
                                            float acc[4][8][4]) {
    int tid = threadIdx.x, lane = tid & 31, w = tid >> 5;
    int wo = w >> 1, wn = w & 1, g = lane >> 2, t = lane & 3;
    stageA(sm, 0, Wsrc, wstride, 0, tid);
    stageB(sm, 0, Xsrc, cs, 0, tid);
    CP_COMMIT();
    for (int c = 0; c < 16; c++) {
        int p = c & 1;
        if (c + 1 < 16) {
            stageA(sm, (c+1) & 1, Wsrc, wstride, c+1, tid);
            stageB(sm, (c+1) & 1, Xsrc, cs, c+1, tid);
            CP_COMMIT();
            CP_WAIT(1);
        } else {
            CP_WAIT(0);
        }
        __syncthreads();
        frag_mma(sm + p*STGF, sm + p*STGF + OFF_B, wo, wn, g, t, acc);
        __syncthreads();
    }
}

__device__ __forceinline__ void acc_to_ys(float* sm, float acc[4][8][4],
                                          int wo, int wn, int g, int t) {
    #pragma unroll
    for (int mi = 0; mi < 4; mi++)
        #pragma unroll
        for (int ni = 0; ni < 8; ni++) {
            int orow = wo*64 + mi*16 + g;
            int ncol = wn*64 + ni*8 + 2*t;
            sm[ncol*YP + orow]       = acc[mi][ni][0];
            sm[(ncol+1)*YP + orow]   = acc[mi][ni][1];
            sm[ncol*YP + orow+8]     = acc[mi][ni][2];
            sm[(ncol+1)*YP + orow+8] = acc[mi][ni][3];
        }
}

// ---------------- gemmG: G[z][m][o] = W1a @ kf ----------------
__global__ __launch_bounds__(256, 1) void gemmG(const float* __restrict__ kf,
                                                const float* __restrict__ W1) {
    extern __shared__ float sm[];
    int tid = threadIdx.x, lane = tid & 31, w = tid >> 5;
    int z = blockIdx.y, b = z >> 2, r = z & 3;
    int m0 = blockIdx.x * 128;
    float acc[4][8][4] = {};
    const float* X = kf + (size_t)b * (C_*NR_*M_) + (size_t)r * M_ + m0;
    mainloop_cp(sm, W1, 512, X, NR_*M_, acc);
    int wo = w >> 1, wn = w & 1, g = lane >> 2, t = lane & 3;
    acc_to_ys(sm, acc, wo, wn, g, t);
    __syncthreads();
    float* Gz = g_G + ((size_t)z * M_ + m0) * C_;
    for (int it = 0; it < 16; it++) {
        int m = it*8 + w;
        #pragma unroll
        for (int j = 0; j < 8; j++) {
            int o = lane + 32*j;
            Gz[(size_t)m * C_ + o] = sm[m*YP + o];
        }
    }
}

// ---------------- gemmY1: y1[z][c][n] = W1b@uf + gather(G); BN1 stats ----------------
__global__ __launch_bounds__(256, 1) void gemmY1(const float* __restrict__ uf,
                                                 const float* __restrict__ W1) {
    extern __shared__ float sm[];
    int tid = threadIdx.x, lane = tid & 31, w = tid >> 5;
    int z = blockIdx.y, b = z >> 2, r = z & 3;
    int n0 = blockIdx.x * 128;
    for (int l = tid; l < 384; l += 256) {
        sm[OFF_W + l]         = g_w  [(b * N_ + n0) * 3 + l];
        ((int*)sm)[OFF_I + l] = g_idx[(b * N_ + n0) * 3 + l];
    }
    sm[OFF_S + tid] = 0.f; sm[OFF_Q + tid] = 0.f;
    float acc[4][8][4] = {};
    const float* X = uf + (size_t)b * (C_*NR_*N_) + (size_t)r * N_ + n0;
    mainloop_cp(sm, W1 + 256, 512, X, NR_*N_, acc);
    int wo = w >> 1, wn = w & 1, g = lane >> 2, t = lane & 3;
    acc_to_ys(sm, acc, wo, wn, g, t);
    __syncthreads();
    // gather + BN1 stats (warp-per-n, lane-per-o, all coalesced/conflict-free)
    const float* Gz = g_G + (size_t)z * M_ * C_;
    float s8[8] = {}, q8[8] = {};
    for (int it = 0; it < 16; it++) {
        int n = it*8 + w;
        float w0 = sm[OFF_W + n*3], w1 = sm[OFF_W + n*3+1], w2 = sm[OFF_W + n*3+2];
        const float* G0 = Gz + (size_t)((int*)sm)[OFF_I + n*3]     * C_;
        const float* G1 = Gz + (size_t)((int*)sm)[OFF_I + n*3 + 1] * C_;
        const float* G2 = Gz + (size_t)((int*)sm)[OFF_I + n*3 + 2] * C_;
        #pragma unroll
        for (int j = 0; j < 8; j++) {
            int o = lane + 32*j;
            float v = sm[n*YP + o] + w0*G0[o] + w1*G1[o] + w2*G2[o];
            sm[n*YP + o] = v;
            s8[j] += v; q8[j] += v*v;
        }
    }
    #pragma unroll
    for (int j = 0; j < 8; j++) {
        atomicAdd(&sm[OFF_S + lane + 32*j], s8[j]);
        atomicAdd(&sm[OFF_Q + lane + 32*j], q8[j]);
    }
    __syncthreads();
    atomicAdd(&g_s1[tid], sm[OFF_S + tid]);
    atomicAdd(&g_q1[tid], sm[OFF_Q + tid]);
    // store y1[z][o][n] (n-contiguous, warp-per-o, lane-per-n)
    float* y1z = g_y1 + (size_t)z * C_ * N_ + n0;
    for (int it = 0; it < 32; it++) {
        int o = it*8 + w;
        #pragma unroll
        for (int j = 0; j < 4; j++) {
            int n = lane + 32*j;
            y1z[(size_t)o * N_ + n] = sm[n*YP + o];
        }
    }
}

// ---------------- gemmZ: out = W2 @ relu(bn1(y1)); BN2 stats ----------------
__global__ __launch_bounds__(256, 1) void gemmZ(const float* __restrict__ W2,
                                                float* __restrict__ out) {
    extern __shared__ float sm[];
    int tid = threadIdx.x, lane = tid & 31, w = tid >> 5;
    int z = blockIdx.y, b = z >> 2, r = z & 3;
    int n0 = blockIdx.x * 128;
    sm[OFF_S + tid] = 0.f; sm[OFF_Q + tid] = 0.f;
    float acc[4][8][4] = {};
    const float* y1z = g_y1 + (size_t)z * C_ * N_ + n0;
    int bk = tid >> 4, bn = (tid & 15) * 8;
    int wo = w >> 1, wn = w & 1, g = lane >> 2, t = lane & 3;

    // register-pipelined B (BN1+ReLU applied in transit), cp.async A
    float4 ca, cb, na, nb4;
    {
        const float* s = y1z + (size_t)bk * N_ + bn;
        ca = *(const float4*)s; cb = *(const float4*)(s + 4);
    }
    stageA(sm, 0, W2, 256, 0, tid);
    CP_COMMIT();
    for (int c = 0; c < 16; c++) {
        int p = c & 1;
        if (c + 1 < 16) { stageA(sm, (c+1) & 1, W2, 256, c+1, tid); CP_COMMIT(); }
        {   // bstore chunk c -> buf p
            float sc = g_scale1[c*16 + bk], bi = g_bias1[c*16 + bk];
            float4 va = ca, vb = cb;
            va.x = fmaxf(fmaf(va.x, sc, bi), 0.f); va.y = fmaxf(fmaf(va.y, sc, bi), 0.f);
            va.z = fmaxf(fmaf(va.z, sc, bi), 0.f); va.w = fmaxf(fmaf(va.w, sc, bi), 0.f);
            vb.x = fmaxf(fmaf(vb.x, sc, bi), 0.f); vb.y = fmaxf(fmaf(vb.y, sc, bi), 0.f);
            vb.z = fmaxf(fmaf(vb.z, sc, bi), 0.f); vb.w = fmaxf(fmaf(vb.w, sc, bi), 0.f);
            float* Bd = sm + p*STGF + OFF_B + bk*BP + bn;
            *(float4*)Bd = va; *(float4*)(Bd + 4) = vb;
        }
        if (c + 1 < 16) {
            const float* s = y1z + (size_t)((c+1)*16 + bk) * N_ + bn;
            na = *(const float4*)s; nb4 = *(const float4*)(s + 4);
            CP_WAIT(1);
        } else {
            CP_WAIT(0);
        }
        __syncthreads();
        frag_mma(sm + p*STGF, sm + p*STGF + OFF_B, wo, wn, g, t, acc);
        __syncthreads();
        ca = na; cb = nb4;
    }

    // BN2 stats from pre-BN accumulators
    {
        float s8[8] = {}, q8[8] = {};
        #pragma unroll
        for (int mi = 0; mi < 4; mi++)
            #pragma unroll
            for (int ni = 0; ni < 8; ni++) {
                float a0 = acc[mi][ni][0], a1 = acc[mi][ni][1];
                float a2 = acc[mi][ni][2], a3 = acc[mi][ni][3];
                s8[mi*2]   += a0 + a1;  q8[mi*2]   += a0*a0 + a1*a1;
                s8[mi*2+1] += a2 + a3;  q8[mi*2+1] += a2*a2 + a3*a3;
            }
        #pragma unroll
        for (int mi = 0; mi < 4; mi++) {
            int orow = wo*64 + mi*16 + g;
            atomicAdd(&sm[OFF_S + orow],     s8[mi*2]);
            atomicAdd(&sm[OFF_Q + orow],     q8[mi*2]);
            atomicAdd(&sm[OFF_S + orow + 8], s8[mi*2+1]);
            atomicAdd(&sm[OFF_Q + orow + 8], q8[mi*2+1]);
        }
    }
    __syncthreads();
    atomicAdd(&g_s2[tid], sm[OFF_S + tid]);
    atomicAdd(&g_q2[tid], sm[OFF_Q + tid]);
    // stage + coalesced store to out[b][o][r][n0+n]
    acc_to_ys(sm, acc, wo, wn, g, t);
    __syncthreads();
    float* ob = out + ((size_t)b * 256 * 4) * 2048 + (size_t)r * 2048 + n0;
    for (int it = 0; it < 32; it++) {
        int o = it*8 + w;
        #pragma unroll
        for (int j = 0; j < 4; j++) {
            int n = lane + 32*j;
            ob[(size_t)o * (4*2048) + n] = sm[n*YP + o];
        }
    }
}

// ---------------- launch ----------------
extern "C" void kernel_launch(void* const* d_in, const int* in_sizes, int n_in,
                              void* d_out, int out_size) {
    const float* unknown = (const float*)d_in[0];
    const float* known   = (const float*)d_in[1];
    const float* uf      = (const float*)d_in[2];
    const float* kf      = (const float*)d_in[3];
    const float* W1      = (const float*)d_in[4];
    const float* g1      = (const float*)d_in[5];
    const float* b1      = (const float*)d_in[6];
    const float* W2      = (const float*)d_in[7];
    const float* g2      = (const float*)d_in[8];
    const float* b2      = (const float*)d_in[9];
    float* out = (float*)d_out;

    static int inited = 0;
    if (!inited) {
        cudaFuncSetAttribute(gemmG,  cudaFuncAttributeMaxDynamicSharedMemorySize, SMEM_BYTES);
        cudaFuncSetAttribute(gemmY1, cudaFuncAttributeMaxDynamicSharedMemorySize, SMEM_BYTES);
        cudaFuncSetAttribute(gemmZ,  cudaFuncAttributeMaxDynamicSharedMemorySize, SMEM_BYTES);
        inited = 1;
    }

    zero_stats_kernel<<<1, 256>>>();
    knn_kernel<<<dim3(N_/256, B_), 256>>>(unknown, known);
    gemmG<<<dim3(M_/128, B_*NR_), 256, SMEM_BYTES>>>(kf, W1);
    gemmY1<<<dim3(N_/128, B_*NR_), 256, SMEM_BYTES>>>(uf, W1);
    bnfin_kernel<<<1, 256>>>(g1, b1, 0);
    gemmZ<<<dim3(N_/128, B_*NR_), 256, SMEM_BYTES>>>(W2, out);
    bnfin_kernel<<<1, 256>>>(g2, b2, 1);
    out_kernel<<<(B_*256*NR_*N_/4) / 256, 256>>>(out);
}